// round 10
// baseline (speedup 1.0000x reference)
#include <cuda_runtime.h>
#include <cuda_fp16.h>
#include <math.h>
#include <stdint.h>

// ---------------------------------------------------------------------------
// DonutSwinLayer: B=16, H=W=64, C=512, NH=16, HD=32, WS=8, N=64, SS=4, MLP=2048
// Round 10: R9 GEMM/LN frozen; attention split-m 128-thread redesign
//           (2 threads/query, shfl-combined softmax+PV, 2x threads per smem).
// ---------------------------------------------------------------------------

#define NTOK   65536
#define CDIM   512
#define NHEADS 16
#define HDIM   32
#define SSH    4
#define MLPD   2048
#define QKVN   1536

#define BM 128
#define BN 128
#define BK 64
#define ROWB 144                    // bytes per smem row (72 halves, LDSM-safe)
#define A_OFF 0
#define B_OFF (BM * ROWB)           // 18432
#define STAGE_B ((BM + BN) * ROWB)  // 36864
#define NSTAGE 2
#define GEMM_SMEM (NSTAGE * STAGE_B)   // 73728

__device__ unsigned char g_scratch[(size_t)26 * NTOK * CDIM + (1u << 24)];

// ============================ helpers ======================================
__device__ __forceinline__ void cp_async16(uint32_t s, const void* g) {
    asm volatile("cp.async.cg.shared.global [%0], [%1], 16;" :: "r"(s), "l"(g));
}
__device__ __forceinline__ void cp_commit() {
    asm volatile("cp.async.commit_group;");
}
template<int N_> __device__ __forceinline__ void cp_wait() {
    asm volatile("cp.async.wait_group %0;" :: "n"(N_));
}
__device__ __forceinline__ void ldsm_x4(uint32_t& r0, uint32_t& r1,
                                        uint32_t& r2, uint32_t& r3, uint32_t a) {
    asm volatile("ldmatrix.sync.aligned.m8n8.x4.shared.b16 {%0,%1,%2,%3}, [%4];"
                 : "=r"(r0), "=r"(r1), "=r"(r2), "=r"(r3) : "r"(a));
}

__global__ void convert_weights_kernel(
    const float* __restrict__ qw, const float* __restrict__ kw,
    const float* __restrict__ vw, const float* __restrict__ pw,
    const float* __restrict__ f1, const float* __restrict__ f2,
    __half* __restrict__ wqkv, __half* __restrict__ wp,
    __half* __restrict__ wf1, __half* __restrict__ wf2) {
    const int CC = 262144, MC = 1048576;
    int i = (blockIdx.x * blockDim.x + threadIdx.x) * 4;
    const float* src; __half* dst; int off;
    if (i < CC)              { src = qw; dst = wqkv;          off = i; }
    else if (i < 2 * CC)     { src = kw; dst = wqkv + CC;     off = i - CC; }
    else if (i < 3 * CC)     { src = vw; dst = wqkv + 2 * CC; off = i - 2 * CC; }
    else if (i < 4 * CC)     { src = pw; dst = wp;            off = i - 3 * CC; }
    else if (i < 4 * CC + MC){ src = f1; dst = wf1;           off = i - 4 * CC; }
    else                     { src = f2; dst = wf2;           off = i - 4 * CC - MC; }
    float4 v = *(const float4*)(src + off);
    *(__half2*)(dst + off)     = __floats2half2_rn(v.x, v.y);
    *(__half2*)(dst + off + 2) = __floats2half2_rn(v.z, v.w);
}

__global__ void concat3_kernel(const float* __restrict__ a,
                               const float* __restrict__ b,
                               const float* __restrict__ c,
                               float* __restrict__ dst) {
    int i = blockIdx.x * blockDim.x + threadIdx.x;
    if (i < 512) dst[i] = a[i];
    else if (i < 1024) dst[i] = b[i - 512];
    else if (i < 1536) dst[i] = c[i - 1024];
}

// ============================ LN kernels (warp per row) ====================
__device__ __forceinline__ void warp_reduce_2(float& s, float& s2) {
    #pragma unroll
    for (int o = 16; o > 0; o >>= 1) {
        s  += __shfl_xor_sync(0xffffffffu, s,  o);
        s2 += __shfl_xor_sync(0xffffffffu, s2, o);
    }
}

__global__ __launch_bounds__(256)
void ln1_gather_kernel(const float* __restrict__ hid,
                       const float* __restrict__ g,
                       const float* __restrict__ b,
                       __half* __restrict__ xw) {
    int wr = blockIdx.x * 8 + (threadIdx.x >> 5);
    int lane = threadIdx.x & 31;
    int b_  = wr >> 12;
    int rem = wr & 4095;
    int wi  = rem >> 6;
    int n   = rem & 63;
    int wh = wi >> 3, ww = wi & 7;
    int i  = n  >> 3, j  = n  & 7;
    int sh_ = ((wh * 8 + i) + SSH) & 63;
    int sw_ = ((ww * 8 + j) + SSH) & 63;
    const float* src = hid + ((size_t)b_ * 4096 + sh_ * 64 + sw_) * CDIM;

    float4 v[4];
    float s = 0.f, s2 = 0.f;
    #pragma unroll
    for (int u = 0; u < 4; u++) {
        v[u] = *(const float4*)(src + lane * 4 + u * 128);
        s  += v[u].x + v[u].y + v[u].z + v[u].w;
        s2 += v[u].x * v[u].x + v[u].y * v[u].y + v[u].z * v[u].z + v[u].w * v[u].w;
    }
    warp_reduce_2(s, s2);
    float mu  = s * (1.f / CDIM);
    float var = s2 * (1.f / CDIM) - mu * mu;
    float inv = rsqrtf(var + 1e-5f);

    __half* dst = xw + (size_t)wr * CDIM;
    #pragma unroll
    for (int u = 0; u < 4; u++) {
        int c = lane * 4 + u * 128;
        float4 gg = *(const float4*)(g + c);
        float4 bb = *(const float4*)(b + c);
        __half2 h0 = __floats2half2_rn((v[u].x - mu) * inv * gg.x + bb.x,
                                       (v[u].y - mu) * inv * gg.y + bb.y);
        __half2 h1 = __floats2half2_rn((v[u].z - mu) * inv * gg.z + bb.z,
                                       (v[u].w - mu) * inv * gg.w + bb.w);
        *(__half2*)(dst + c)     = h0;
        *(__half2*)(dst + c + 2) = h1;
    }
}

__global__ __launch_bounds__(256)
void ln_plain_kernel(const float* __restrict__ x,
                     const float* __restrict__ g,
                     const float* __restrict__ b,
                     __half* __restrict__ y) {
    int r = blockIdx.x * 8 + (threadIdx.x >> 5);
    int lane = threadIdx.x & 31;
    const float* src = x + (size_t)r * CDIM;
    float4 v[4];
    float s = 0.f, s2 = 0.f;
    #pragma unroll
    for (int u = 0; u < 4; u++) {
        v[u] = *(const float4*)(src + lane * 4 + u * 128);
        s  += v[u].x + v[u].y + v[u].z + v[u].w;
        s2 += v[u].x * v[u].x + v[u].y * v[u].y + v[u].z * v[u].z + v[u].w * v[u].w;
    }
    warp_reduce_2(s, s2);
    float mu  = s * (1.f / CDIM);
    float var = s2 * (1.f / CDIM) - mu * mu;
    float inv = rsqrtf(var + 1e-5f);
    __half* dst = y + (size_t)r * CDIM;
    #pragma unroll
    for (int u = 0; u < 4; u++) {
        int c = lane * 4 + u * 128;
        float4 gg = *(const float4*)(g + c);
        float4 bb = *(const float4*)(b + c);
        __half2 h0 = __floats2half2_rn((v[u].x - mu) * inv * gg.x + bb.x,
                                       (v[u].y - mu) * inv * gg.y + bb.y);
        __half2 h1 = __floats2half2_rn((v[u].z - mu) * inv * gg.z + bb.z,
                                       (v[u].w - mu) * inv * gg.w + bb.w);
        *(__half2*)(dst + c)     = h0;
        *(__half2*)(dst + c + 2) = h1;
    }
}

// ============================ fp16 GEMM (R9 config, frozen) ================
// 256 threads, 8 warps 4M x 2N, warp tile 32x64. ldmatrix, BK=64, 2-stage.
// mode: 0 half out, 1 gelu->half, 2 float+residual, 4 float+scatter+residual
__global__ __launch_bounds__(256, 2)
void gemm_f16_kernel(const __half* __restrict__ A, const __half* __restrict__ W,
                     const float* __restrict__ bias, void* __restrict__ Cout,
                     int N, int K, int mode, const float* __restrict__ add) {
    extern __shared__ char smem[];
    uint32_t sb = (uint32_t)__cvta_generic_to_shared(smem);

    const int tid  = threadIdx.x;
    const int warp = tid >> 5;
    const int lane = tid & 31;
    const int bm   = blockIdx.y * BM;
    const int bn   = blockIdx.x * BN;
    const int wm   = (warp & 3) * 32;
    const int wn   = (warp >> 2) * 64;
    const int lr   = lane >> 2;
    const int lc   = lane & 3;

    uint32_t aAddr[2], bAddr[4];
    {
        int arow = wm + (lane & 15);
        int akof = (lane >> 4) * 16;
        #pragma unroll
        for (int mt = 0; mt < 2; mt++)
            aAddr[mt] = sb + A_OFF + (uint32_t)((arow + mt * 16) * ROWB + akof);
        int brow = wn + (lane & 7) + ((lane >> 4) << 3);
        int bkof = ((lane >> 3) & 1) << 4;
        #pragma unroll
        for (int p = 0; p < 4; p++)
            bAddr[p] = sb + B_OFF + (uint32_t)((brow + p * 16) * ROWB + bkof);
    }

    float acc[2][8][4];
    #pragma unroll
    for (int mt = 0; mt < 2; mt++)
        #pragma unroll
        for (int nt = 0; nt < 8; nt++)
            #pragma unroll
            for (int r = 0; r < 4; r++) acc[mt][nt][r] = 0.f;

    const int KT = K / BK;

    auto load_tile = [&](int buf, int k0) {
        uint32_t sbase = sb + (uint32_t)(buf * STAGE_B);
        #pragma unroll
        for (int u = 0; u < 4; u++) {
            int ch = tid + u * 256;
            int row = ch >> 3, kq = ch & 7;
            cp_async16(sbase + A_OFF + (uint32_t)(row * ROWB + kq * 16),
                       A + (size_t)(bm + row) * K + k0 + kq * 8);
        }
        #pragma unroll
        for (int u = 0; u < 4; u++) {
            int ch = tid + u * 256;
            int row = ch >> 3, kq = ch & 7;
            cp_async16(sbase + B_OFF + (uint32_t)(row * ROWB + kq * 16),
                       W + (size_t)(bn + row) * K + k0 + kq * 8);
        }
        cp_commit();
    };

    load_tile(0, 0);

    for (int kt = 0; kt < KT; kt++) {
        int cur = kt & 1;
        if (kt + 1 < KT) {
            load_tile(cur ^ 1, (kt + 1) * BK);
            cp_wait<1>();
        } else {
            cp_wait<0>();
        }
        __syncthreads();

        uint32_t soff = (uint32_t)(cur * STAGE_B);
        #pragma unroll
        for (int ks = 0; ks < BK; ks += 16) {
            uint32_t af[2][4], bf[8][2];
            #pragma unroll
            for (int mt = 0; mt < 2; mt++)
                ldsm_x4(af[mt][0], af[mt][1], af[mt][2], af[mt][3],
                        aAddr[mt] + soff + ks * 2);
            #pragma unroll
            for (int p = 0; p < 4; p++)
                ldsm_x4(bf[2 * p][0], bf[2 * p][1], bf[2 * p + 1][0],
                        bf[2 * p + 1][1], bAddr[p] + soff + ks * 2);
            #pragma unroll
            for (int mt = 0; mt < 2; mt++)
                #pragma unroll
                for (int nt = 0; nt < 8; nt++) {
                    asm volatile(
                        "mma.sync.aligned.m16n8k16.row.col.f32.f16.f16.f32 "
                        "{%0,%1,%2,%3}, {%4,%5,%6,%7}, {%8,%9}, {%0,%1,%2,%3};\n"
                        : "+f"(acc[mt][nt][0]), "+f"(acc[mt][nt][1]),
                          "+f"(acc[mt][nt][2]), "+f"(acc[mt][nt][3])
                        : "r"(af[mt][0]), "r"(af[mt][1]), "r"(af[mt][2]), "r"(af[mt][3]),
                          "r"(bf[nt][0]), "r"(bf[nt][1]));
                }
        }
        __syncthreads();
    }

    // epilogue
    #pragma unroll
    for (int mt = 0; mt < 2; mt++) {
        #pragma unroll
        for (int h = 0; h < 2; h++) {
            int row = bm + wm + mt * 16 + lr + h * 8;
            size_t orow = (size_t)row;
            if (mode == 4) {
                int b_ = row >> 12, wi = (row >> 6) & 63, n = row & 63;
                int wh = wi >> 3, ww = wi & 7, i = n >> 3, j = n & 7;
                int sh_ = ((wh * 8 + i) + SSH) & 63;
                int sw_ = ((ww * 8 + j) + SSH) & 63;
                orow = (size_t)b_ * 4096 + sh_ * 64 + sw_;
            }
            #pragma unroll
            for (int nt = 0; nt < 8; nt++) {
                int col = bn + wn + nt * 8 + 2 * lc;
                float v0 = acc[mt][nt][2 * h + 0] + bias[col];
                float v1 = acc[mt][nt][2 * h + 1] + bias[col + 1];
                if (mode == 1) {
                    v0 = 0.5f * v0 * (1.f + erff(v0 * 0.70710678118654752f));
                    v1 = 0.5f * v1 * (1.f + erff(v1 * 0.70710678118654752f));
                }
                if (mode <= 1) {
                    __half* crow = (__half*)Cout + (size_t)row * N + col;
                    *(__half2*)crow = __floats2half2_rn(v0, v1);
                } else {
                    const float* ar = add + orow * N + col;
                    v0 += ar[0]; v1 += ar[1];
                    float* crow = (float*)Cout + orow * N + col;
                    crow[0] = v0; crow[1] = v1;
                }
            }
        }
    }
}

// ============================ attention ====================================
// one block per (window, head), 128 threads: 2 threads per query, split over
// the key dimension (thread (q,mh) owns m in [32*mh, 32*mh+32)). All pair
// combines via shfl_xor(1) (adjacent lanes). Same smem as before -> 2x
// threads per SM for the same footprint.
__global__ __launch_bounds__(128, 9)
void attn_kernel(const __half* __restrict__ qkv, const float* __restrict__ btab,
                 __half* __restrict__ ctx) {
    __shared__ __half2 ks2[64][16];
    __shared__ __half2 vs2[64][16];
    __shared__ float   sc[64][65];
    __shared__ int     rid[64];

    int win  = blockIdx.x;
    int head = blockIdx.y;
    int tid  = threadIdx.x;
    int q    = tid >> 1;      // query 0..63
    int mh   = tid & 1;       // key-half 0/1

    int wi = win & 63;
    int wh = wi >> 3, ww = wi & 7;
    int iq = q >> 3, jq = q & 7;

    size_t rowb = ((size_t)win * 64 + q) * QKVN;
    {
        const uint4* kp = (const uint4*)(qkv + rowb + 512 + head * 32);
        const uint4* vp = (const uint4*)(qkv + rowb + 1024 + head * 32);
        ((uint4*)ks2[q])[2 * mh]     = kp[2 * mh];
        ((uint4*)ks2[q])[2 * mh + 1] = kp[2 * mh + 1];
        ((uint4*)vs2[q])[2 * mh]     = vp[2 * mh];
        ((uint4*)vs2[q])[2 * mh + 1] = vp[2 * mh + 1];
    }
    if (mh == 0) {
        int hs = wh * 8 + iq, wc = ww * 8 + jq;
        int rh = (hs < 56) ? 0 : ((hs < 60) ? 1 : 2);
        int rw = (wc < 56) ? 0 : ((wc < 60) ? 1 : 2);
        rid[q] = rh * 3 + rw;
    }
    float qr[32];
    {
        const __half2* qp = (const __half2*)(qkv + rowb + head * 32);
        #pragma unroll
        for (int u = 0; u < 16; u++) {
            float2 a = __half22float2(qp[u]);
            qr[2 * u] = a.x; qr[2 * u + 1] = a.y;
        }
    }
    __syncthreads();

    const float scale = 0.17677669529663687f;
    int myrid = rid[q];
    int m0 = mh * 32;

    // QK over own 32 keys
    float mx = -1e30f;
    for (int mm = 0; mm < 32; mm++) {
        int m = m0 + mm;
        float acc = 0.f;
        #pragma unroll
        for (int d2 = 0; d2 < 16; d2++) {
            float2 kv = __half22float2(ks2[m][d2]);
            acc += qr[2 * d2] * kv.x + qr[2 * d2 + 1] * kv.y;
        }
        int hk = m >> 3, wk = m & 7;
        int bidx = (iq - hk + 7) * 15 + (jq - wk + 7);
        float bv = btab[bidx * NHEADS + head];
        float msk = (rid[m] == myrid) ? 0.f : -100.f;
        float s = acc * scale + bv + msk;
        sc[q][m] = s;
        mx = fmaxf(mx, s);
    }
    mx = fmaxf(mx, __shfl_xor_sync(0xffffffffu, mx, 1));

    float sum = 0.f;
    for (int mm = 0; mm < 32; mm++) {
        float e = __expf(sc[q][m0 + mm] - mx);
        sc[q][m0 + mm] = e;
        sum += e;
    }
    sum += __shfl_xor_sync(0xffffffffu, sum, 1);
    float inv = 1.f / sum;

    // PV over own 32 keys, full 32-dim accumulator
    float accv[32];
    #pragma unroll
    for (int d = 0; d < 32; d++) accv[d] = 0.f;
    for (int mm = 0; mm < 32; mm++) {
        int m = m0 + mm;
        float p = sc[q][m];
        #pragma unroll
        for (int d2 = 0; d2 < 16; d2++) {
            float2 vv = __half22float2(vs2[m][d2]);
            accv[2 * d2]     += p * vv.x;
            accv[2 * d2 + 1] += p * vv.y;
        }
    }
    // butterfly: both pair threads end with full sums
    #pragma unroll
    for (int d = 0; d < 32; d++)
        accv[d] += __shfl_xor_sync(0xffffffffu, accv[d], 1);

    // each pair thread writes its 16 output dims
    __half* o = ctx + ((size_t)win * 64 + q) * CDIM + head * 32 + mh * 16;
    #pragma unroll
    for (int d = 0; d < 16; d += 2)
        *(__half2*)(o + d) = __floats2half2_rn(accv[mh * 16 + d] * inv,
                                               accv[mh * 16 + d + 1] * inv);
}

// ============================ launch =======================================
extern "C" void kernel_launch(void* const* d_in, const int* in_sizes, int n_in,
                              void* d_out, int out_size) {
    const float* hid    = (const float*)d_in[0];
    const float* q_w    = (const float*)d_in[1];
    const float* q_b    = (const float*)d_in[2];
    const float* k_w    = (const float*)d_in[3];
    const float* k_b    = (const float*)d_in[4];
    const float* v_w    = (const float*)d_in[5];
    const float* v_b    = (const float*)d_in[6];
    const float* proj_w = (const float*)d_in[7];
    const float* proj_b = (const float*)d_in[8];
    const float* relb   = (const float*)d_in[9];
    const float* ln1w   = (const float*)d_in[10];
    const float* ln1b   = (const float*)d_in[11];
    const float* ln2w   = (const float*)d_in[12];
    const float* ln2b   = (const float*)d_in[13];
    const float* fc1w   = (const float*)d_in[14];
    const float* fc1b   = (const float*)d_in[15];
    const float* fc2w   = (const float*)d_in[16];
    const float* fc2b   = (const float*)d_in[17];

    unsigned char* base = nullptr;
    cudaGetSymbolAddress((void**)&base, g_scratch);
    const size_t TC = (size_t)NTOK * CDIM;
    __half* xw   = (__half*)base;
    __half* qkvb = (__half*)(base + TC * 2);
    __half* cx   = (__half*)(base + TC * 8);
    float*  hb   = (float*)(base + TC * 10);
    __half* yb   = (__half*)(base + TC * 14);
    __half* mlp  = (__half*)(base + TC * 16);
    unsigned char* wbase = base + TC * 24;
    const size_t CC = (size_t)CDIM * CDIM, MC = (size_t)MLPD * CDIM;
    __half* wqkv = (__half*)wbase;
    __half* wp   = wqkv + 3 * CC;
    __half* wf1  = wp + CC;
    __half* wf2  = wf1 + MC;
    float*  qkvbias = (float*)(wf2 + MC);

    float* out = (float*)d_out;

    cudaFuncSetAttribute(gemm_f16_kernel,
                         cudaFuncAttributeMaxDynamicSharedMemorySize, GEMM_SMEM);

    convert_weights_kernel<<<3072, 256>>>(q_w, k_w, v_w, proj_w, fc1w, fc2w,
                                          wqkv, wp, wf1, wf2);
    concat3_kernel<<<6, 256>>>(q_b, k_b, v_b, qkvbias);

    ln1_gather_kernel<<<NTOK / 8, 256>>>(hid, ln1w, ln1b, xw);

    gemm_f16_kernel<<<dim3(QKVN / BN, NTOK / BM), 256, GEMM_SMEM>>>(
        xw, wqkv, qkvbias, qkvb, QKVN, CDIM, 0, nullptr);

    attn_kernel<<<dim3(1024, NHEADS), 128>>>(qkvb, relb, cx);

    gemm_f16_kernel<<<dim3(CDIM / BN, NTOK / BM), 256, GEMM_SMEM>>>(
        cx, wp, proj_b, hb, CDIM, CDIM, 4, hid);

    ln_plain_kernel<<<NTOK / 8, 256>>>(hb, ln2w, ln2b, yb);

    gemm_f16_kernel<<<dim3(MLPD / BN, NTOK / BM), 256, GEMM_SMEM>>>(
        yb, wf1, fc1b, mlp, MLPD, CDIM, 1, nullptr);

    gemm_f16_kernel<<<dim3(CDIM / BN, NTOK / BM), 256, GEMM_SMEM>>>(
        mlp, wf2, fc2b, out, CDIM, MLPD, 2, hb);
}

// round 11
// speedup vs baseline: 1.0782x; 1.0782x over previous
#include <cuda_runtime.h>
#include <cuda_fp16.h>
#include <math.h>
#include <stdint.h>

// ---------------------------------------------------------------------------
// DonutSwinLayer: B=16, H=W=64, C=512, NH=16, HD=32, WS=8, N=64, SS=4, MLP=2048
// Round 11: R9 base; QKV written head-major ([win][head][n][32]) so attention
//           loads are coalesced; bias table staged in smem. Attention = R9 body.
// ---------------------------------------------------------------------------

#define NTOK   65536
#define CDIM   512
#define NHEADS 16
#define HDIM   32
#define SSH    4
#define MLPD   2048
#define QKVN   1536
#define TCH    33554432ULL          // NTOK*CDIM (halves per q/k/v plane)

#define BM 128
#define BN 128
#define BK 64
#define ROWB 144                    // bytes per smem row (72 halves, LDSM-safe)
#define A_OFF 0
#define B_OFF (BM * ROWB)           // 18432
#define STAGE_B ((BM + BN) * ROWB)  // 36864
#define NSTAGE 2
#define GEMM_SMEM (NSTAGE * STAGE_B)   // 73728

__device__ unsigned char g_scratch[(size_t)26 * NTOK * CDIM + (1u << 24)];

// ============================ helpers ======================================
__device__ __forceinline__ void cp_async16(uint32_t s, const void* g) {
    asm volatile("cp.async.cg.shared.global [%0], [%1], 16;" :: "r"(s), "l"(g));
}
__device__ __forceinline__ void cp_commit() {
    asm volatile("cp.async.commit_group;");
}
template<int N_> __device__ __forceinline__ void cp_wait() {
    asm volatile("cp.async.wait_group %0;" :: "n"(N_));
}
__device__ __forceinline__ void ldsm_x4(uint32_t& r0, uint32_t& r1,
                                        uint32_t& r2, uint32_t& r3, uint32_t a) {
    asm volatile("ldmatrix.sync.aligned.m8n8.x4.shared.b16 {%0,%1,%2,%3}, [%4];"
                 : "=r"(r0), "=r"(r1), "=r"(r2), "=r"(r3) : "r"(a));
}

__global__ void convert_weights_kernel(
    const float* __restrict__ qw, const float* __restrict__ kw,
    const float* __restrict__ vw, const float* __restrict__ pw,
    const float* __restrict__ f1, const float* __restrict__ f2,
    __half* __restrict__ wqkv, __half* __restrict__ wp,
    __half* __restrict__ wf1, __half* __restrict__ wf2) {
    const int CC = 262144, MC = 1048576;
    int i = (blockIdx.x * blockDim.x + threadIdx.x) * 4;
    const float* src; __half* dst; int off;
    if (i < CC)              { src = qw; dst = wqkv;          off = i; }
    else if (i < 2 * CC)     { src = kw; dst = wqkv + CC;     off = i - CC; }
    else if (i < 3 * CC)     { src = vw; dst = wqkv + 2 * CC; off = i - 2 * CC; }
    else if (i < 4 * CC)     { src = pw; dst = wp;            off = i - 3 * CC; }
    else if (i < 4 * CC + MC){ src = f1; dst = wf1;           off = i - 4 * CC; }
    else                     { src = f2; dst = wf2;           off = i - 4 * CC - MC; }
    float4 v = *(const float4*)(src + off);
    *(__half2*)(dst + off)     = __floats2half2_rn(v.x, v.y);
    *(__half2*)(dst + off + 2) = __floats2half2_rn(v.z, v.w);
}

__global__ void concat3_kernel(const float* __restrict__ a,
                               const float* __restrict__ b,
                               const float* __restrict__ c,
                               float* __restrict__ dst) {
    int i = blockIdx.x * blockDim.x + threadIdx.x;
    if (i < 512) dst[i] = a[i];
    else if (i < 1024) dst[i] = b[i - 512];
    else if (i < 1536) dst[i] = c[i - 1024];
}

// ============================ LN kernels (warp per row) ====================
__device__ __forceinline__ void warp_reduce_2(float& s, float& s2) {
    #pragma unroll
    for (int o = 16; o > 0; o >>= 1) {
        s  += __shfl_xor_sync(0xffffffffu, s,  o);
        s2 += __shfl_xor_sync(0xffffffffu, s2, o);
    }
}

__global__ __launch_bounds__(256)
void ln1_gather_kernel(const float* __restrict__ hid,
                       const float* __restrict__ g,
                       const float* __restrict__ b,
                       __half* __restrict__ xw) {
    int wr = blockIdx.x * 8 + (threadIdx.x >> 5);
    int lane = threadIdx.x & 31;
    int b_  = wr >> 12;
    int rem = wr & 4095;
    int wi  = rem >> 6;
    int n   = rem & 63;
    int wh = wi >> 3, ww = wi & 7;
    int i  = n  >> 3, j  = n  & 7;
    int sh_ = ((wh * 8 + i) + SSH) & 63;
    int sw_ = ((ww * 8 + j) + SSH) & 63;
    const float* src = hid + ((size_t)b_ * 4096 + sh_ * 64 + sw_) * CDIM;

    float4 v[4];
    float s = 0.f, s2 = 0.f;
    #pragma unroll
    for (int u = 0; u < 4; u++) {
        v[u] = *(const float4*)(src + lane * 4 + u * 128);
        s  += v[u].x + v[u].y + v[u].z + v[u].w;
        s2 += v[u].x * v[u].x + v[u].y * v[u].y + v[u].z * v[u].z + v[u].w * v[u].w;
    }
    warp_reduce_2(s, s2);
    float mu  = s * (1.f / CDIM);
    float var = s2 * (1.f / CDIM) - mu * mu;
    float inv = rsqrtf(var + 1e-5f);

    __half* dst = xw + (size_t)wr * CDIM;
    #pragma unroll
    for (int u = 0; u < 4; u++) {
        int c = lane * 4 + u * 128;
        float4 gg = *(const float4*)(g + c);
        float4 bb = *(const float4*)(b + c);
        __half2 h0 = __floats2half2_rn((v[u].x - mu) * inv * gg.x + bb.x,
                                       (v[u].y - mu) * inv * gg.y + bb.y);
        __half2 h1 = __floats2half2_rn((v[u].z - mu) * inv * gg.z + bb.z,
                                       (v[u].w - mu) * inv * gg.w + bb.w);
        *(__half2*)(dst + c)     = h0;
        *(__half2*)(dst + c + 2) = h1;
    }
}

__global__ __launch_bounds__(256)
void ln_plain_kernel(const float* __restrict__ x,
                     const float* __restrict__ g,
                     const float* __restrict__ b,
                     __half* __restrict__ y) {
    int r = blockIdx.x * 8 + (threadIdx.x >> 5);
    int lane = threadIdx.x & 31;
    const float* src = x + (size_t)r * CDIM;
    float4 v[4];
    float s = 0.f, s2 = 0.f;
    #pragma unroll
    for (int u = 0; u < 4; u++) {
        v[u] = *(const float4*)(src + lane * 4 + u * 128);
        s  += v[u].x + v[u].y + v[u].z + v[u].w;
        s2 += v[u].x * v[u].x + v[u].y * v[u].y + v[u].z * v[u].z + v[u].w * v[u].w;
    }
    warp_reduce_2(s, s2);
    float mu  = s * (1.f / CDIM);
    float var = s2 * (1.f / CDIM) - mu * mu;
    float inv = rsqrtf(var + 1e-5f);
    __half* dst = y + (size_t)r * CDIM;
    #pragma unroll
    for (int u = 0; u < 4; u++) {
        int c = lane * 4 + u * 128;
        float4 gg = *(const float4*)(g + c);
        float4 bb = *(const float4*)(b + c);
        __half2 h0 = __floats2half2_rn((v[u].x - mu) * inv * gg.x + bb.x,
                                       (v[u].y - mu) * inv * gg.y + bb.y);
        __half2 h1 = __floats2half2_rn((v[u].z - mu) * inv * gg.z + bb.z,
                                       (v[u].w - mu) * inv * gg.w + bb.w);
        *(__half2*)(dst + c)     = h0;
        *(__half2*)(dst + c + 2) = h1;
    }
}

// ============================ fp16 GEMM (R9 mainloop) ======================
// mode: 0 qkv head-major scatter (half), 1 gelu->half, 2 float+residual,
//       4 float+window-reverse-scatter+residual
__global__ __launch_bounds__(256, 2)
void gemm_f16_kernel(const __half* __restrict__ A, const __half* __restrict__ W,
                     const float* __restrict__ bias, void* __restrict__ Cout,
                     int N, int K, int mode, const float* __restrict__ add) {
    extern __shared__ char smem[];
    uint32_t sb = (uint32_t)__cvta_generic_to_shared(smem);

    const int tid  = threadIdx.x;
    const int warp = tid >> 5;
    const int lane = tid & 31;
    const int bm   = blockIdx.y * BM;
    const int bn   = blockIdx.x * BN;
    const int wm   = (warp & 3) * 32;
    const int wn   = (warp >> 2) * 64;
    const int lr   = lane >> 2;
    const int lc   = lane & 3;

    uint32_t aAddr[2], bAddr[4];
    {
        int arow = wm + (lane & 15);
        int akof = (lane >> 4) * 16;
        #pragma unroll
        for (int mt = 0; mt < 2; mt++)
            aAddr[mt] = sb + A_OFF + (uint32_t)((arow + mt * 16) * ROWB + akof);
        int brow = wn + (lane & 7) + ((lane >> 4) << 3);
        int bkof = ((lane >> 3) & 1) << 4;
        #pragma unroll
        for (int p = 0; p < 4; p++)
            bAddr[p] = sb + B_OFF + (uint32_t)((brow + p * 16) * ROWB + bkof);
    }

    float acc[2][8][4];
    #pragma unroll
    for (int mt = 0; mt < 2; mt++)
        #pragma unroll
        for (int nt = 0; nt < 8; nt++)
            #pragma unroll
            for (int r = 0; r < 4; r++) acc[mt][nt][r] = 0.f;

    const int KT = K / BK;

    auto load_tile = [&](int buf, int k0) {
        uint32_t sbase = sb + (uint32_t)(buf * STAGE_B);
        #pragma unroll
        for (int u = 0; u < 4; u++) {
            int ch = tid + u * 256;
            int row = ch >> 3, kq = ch & 7;
            cp_async16(sbase + A_OFF + (uint32_t)(row * ROWB + kq * 16),
                       A + (size_t)(bm + row) * K + k0 + kq * 8);
        }
        #pragma unroll
        for (int u = 0; u < 4; u++) {
            int ch = tid + u * 256;
            int row = ch >> 3, kq = ch & 7;
            cp_async16(sbase + B_OFF + (uint32_t)(row * ROWB + kq * 16),
                       W + (size_t)(bn + row) * K + k0 + kq * 8);
        }
        cp_commit();
    };

    load_tile(0, 0);

    for (int kt = 0; kt < KT; kt++) {
        int cur = kt & 1;
        if (kt + 1 < KT) {
            load_tile(cur ^ 1, (kt + 1) * BK);
            cp_wait<1>();
        } else {
            cp_wait<0>();
        }
        __syncthreads();

        uint32_t soff = (uint32_t)(cur * STAGE_B);
        #pragma unroll
        for (int ks = 0; ks < BK; ks += 16) {
            uint32_t af[2][4], bf[8][2];
            #pragma unroll
            for (int mt = 0; mt < 2; mt++)
                ldsm_x4(af[mt][0], af[mt][1], af[mt][2], af[mt][3],
                        aAddr[mt] + soff + ks * 2);
            #pragma unroll
            for (int p = 0; p < 4; p++)
                ldsm_x4(bf[2 * p][0], bf[2 * p][1], bf[2 * p + 1][0],
                        bf[2 * p + 1][1], bAddr[p] + soff + ks * 2);
            #pragma unroll
            for (int mt = 0; mt < 2; mt++)
                #pragma unroll
                for (int nt = 0; nt < 8; nt++) {
                    asm volatile(
                        "mma.sync.aligned.m16n8k16.row.col.f32.f16.f16.f32 "
                        "{%0,%1,%2,%3}, {%4,%5,%6,%7}, {%8,%9}, {%0,%1,%2,%3};\n"
                        : "+f"(acc[mt][nt][0]), "+f"(acc[mt][nt][1]),
                          "+f"(acc[mt][nt][2]), "+f"(acc[mt][nt][3])
                        : "r"(af[mt][0]), "r"(af[mt][1]), "r"(af[mt][2]), "r"(af[mt][3]),
                          "r"(bf[nt][0]), "r"(bf[nt][1]));
                }
        }
        __syncthreads();
    }

    // epilogue
    #pragma unroll
    for (int mt = 0; mt < 2; mt++) {
        #pragma unroll
        for (int h = 0; h < 2; h++) {
            int row = bm + wm + mt * 16 + lr + h * 8;
            size_t orow = (size_t)row;
            if (mode == 4) {
                int b_ = row >> 12, wi = (row >> 6) & 63, n = row & 63;
                int wh = wi >> 3, ww = wi & 7, i = n >> 3, j = n & 7;
                int sh_ = ((wh * 8 + i) + SSH) & 63;
                int sw_ = ((ww * 8 + j) + SSH) & 63;
                orow = (size_t)b_ * 4096 + sh_ * 64 + sw_;
            }
            #pragma unroll
            for (int nt = 0; nt < 8; nt++) {
                int col = bn + wn + nt * 8 + 2 * lc;
                float v0 = acc[mt][nt][2 * h + 0] + bias[col];
                float v1 = acc[mt][nt][2 * h + 1] + bias[col + 1];
                if (mode == 0) {
                    // head-major qkv scatter: [which][win][head][n][32]
                    int which = col >> 9;
                    int hc = col & 511;
                    int head = hc >> 5, d = hc & 31;
                    size_t off = (size_t)which * TCH +
                        ((((size_t)(row >> 6) * NHEADS + head) * 64) +
                         (row & 63)) * 32 + d;
                    *(__half2*)((__half*)Cout + off) = __floats2half2_rn(v0, v1);
                } else if (mode == 1) {
                    v0 = 0.5f * v0 * (1.f + erff(v0 * 0.70710678118654752f));
                    v1 = 0.5f * v1 * (1.f + erff(v1 * 0.70710678118654752f));
                    __half* crow = (__half*)Cout + (size_t)row * N + col;
                    *(__half2*)crow = __floats2half2_rn(v0, v1);
                } else {
                    const float* ar = add + orow * N + col;
                    v0 += ar[0]; v1 += ar[1];
                    float* crow = (float*)Cout + orow * N + col;
                    crow[0] = v0; crow[1] = v1;
                }
            }
        }
    }
}

// ============================ attention ====================================
// one block per (window, head), 64 threads. qkv in head-major layout:
// plane which: [win][head][n][32] halves. Coalesced 4KB tile loads.
// Bias table staged in smem. Body = R9 (PV halves, __expf).
__global__ __launch_bounds__(64, 12)
void attn_kernel(const __half* __restrict__ qkv, const float* __restrict__ btab,
                 __half* __restrict__ ctx) {
    __shared__ __half2 ks2[64][16];
    __shared__ __half2 vs2[64][16];
    __shared__ float   sc[64][65];
    __shared__ float   sbias[225];
    __shared__ int     rid[64];

    int win  = blockIdx.x;
    int head = blockIdx.y;
    int n    = threadIdx.x;

    int wi = win & 63;
    int wh = wi >> 3, ww = wi & 7;
    int i  = n  >> 3, j  = n  & 7;

    int hs = wh * 8 + i, wc = ww * 8 + j;
    int rh = (hs < 56) ? 0 : ((hs < 60) ? 1 : 2);
    int rw = (wc < 56) ? 0 : ((wc < 60) ? 1 : 2);
    rid[n] = rh * 3 + rw;

    size_t hbase = (((size_t)win * NHEADS + head) * 64) * 32;  // halves
    const uint4* kp = (const uint4*)(qkv + TCH + hbase + (size_t)n * 32);
    const uint4* vp = (const uint4*)(qkv + 2 * TCH + hbase + (size_t)n * 32);
    #pragma unroll
    for (int u = 0; u < 4; u++) {
        ((uint4*)ks2[n])[u] = kp[u];
        ((uint4*)vs2[n])[u] = vp[u];
    }
    float qr[32];
    {
        const __half2* qp = (const __half2*)(qkv + hbase + (size_t)n * 32);
        #pragma unroll
        for (int u = 0; u < 16; u++) {
            float2 a = __half22float2(qp[u]);
            qr[2 * u] = a.x; qr[2 * u + 1] = a.y;
        }
    }
    // stage bias table for this head
    for (int t = n; t < 225; t += 64) sbias[t] = btab[t * NHEADS + head];
    __syncthreads();

    const float scale = 0.17677669529663687f;
    int myrid = rid[n];

    float mx = -1e30f;
    for (int m = 0; m < 64; m++) {
        float acc = 0.f;
        #pragma unroll
        for (int d2 = 0; d2 < 16; d2++) {
            float2 kv = __half22float2(ks2[m][d2]);
            acc += qr[2 * d2] * kv.x + qr[2 * d2 + 1] * kv.y;
        }
        int hk = m >> 3, wk = m & 7;
        int bidx = (i - hk + 7) * 15 + (j - wk + 7);
        float bv = sbias[bidx];
        float msk = (rid[m] == myrid) ? 0.f : -100.f;
        float s = acc * scale + bv + msk;
        sc[n][m] = s;
        mx = fmaxf(mx, s);
    }

    float sum = 0.f;
    for (int m = 0; m < 64; m++) {
        float e = __expf(sc[n][m] - mx);
        sc[n][m] = e;
        sum += e;
    }
    float inv = 1.f / sum;
    __half* o = ctx + ((size_t)win * 64 + n) * CDIM + head * 32;

    #pragma unroll
    for (int half_ = 0; half_ < 2; half_++) {
        float accv[16];
        #pragma unroll
        for (int d = 0; d < 16; d++) accv[d] = 0.f;
        for (int m = 0; m < 64; m++) {
            float p = sc[n][m];
            #pragma unroll
            for (int d2 = 0; d2 < 8; d2++) {
                float2 vv = __half22float2(vs2[m][half_ * 8 + d2]);
                accv[2 * d2]     += p * vv.x;
                accv[2 * d2 + 1] += p * vv.y;
            }
        }
        #pragma unroll
        for (int d = 0; d < 16; d += 2)
            *(__half2*)(o + half_ * 16 + d) =
                __floats2half2_rn(accv[d] * inv, accv[d + 1] * inv);
    }
}

// ============================ launch =======================================
extern "C" void kernel_launch(void* const* d_in, const int* in_sizes, int n_in,
                              void* d_out, int out_size) {
    const float* hid    = (const float*)d_in[0];
    const float* q_w    = (const float*)d_in[1];
    const float* q_b    = (const float*)d_in[2];
    const float* k_w    = (const float*)d_in[3];
    const float* k_b    = (const float*)d_in[4];
    const float* v_w    = (const float*)d_in[5];
    const float* v_b    = (const float*)d_in[6];
    const float* proj_w = (const float*)d_in[7];
    const float* proj_b = (const float*)d_in[8];
    const float* relb   = (const float*)d_in[9];
    const float* ln1w   = (const float*)d_in[10];
    const float* ln1b   = (const float*)d_in[11];
    const float* ln2w   = (const float*)d_in[12];
    const float* ln2b   = (const float*)d_in[13];
    const float* fc1w   = (const float*)d_in[14];
    const float* fc1b   = (const float*)d_in[15];
    const float* fc2w   = (const float*)d_in[16];
    const float* fc2b   = (const float*)d_in[17];

    unsigned char* base = nullptr;
    cudaGetSymbolAddress((void**)&base, g_scratch);
    const size_t TC = (size_t)NTOK * CDIM;
    __half* xw   = (__half*)base;
    __half* qkvb = (__half*)(base + TC * 2);
    __half* cx   = (__half*)(base + TC * 8);
    float*  hb   = (float*)(base + TC * 10);
    __half* yb   = (__half*)(base + TC * 14);
    __half* mlp  = (__half*)(base + TC * 16);
    unsigned char* wbase = base + TC * 24;
    const size_t CC = (size_t)CDIM * CDIM, MC = (size_t)MLPD * CDIM;
    __half* wqkv = (__half*)wbase;
    __half* wp   = wqkv + 3 * CC;
    __half* wf1  = wp + CC;
    __half* wf2  = wf1 + MC;
    float*  qkvbias = (float*)(wf2 + MC);

    float* out = (float*)d_out;

    cudaFuncSetAttribute(gemm_f16_kernel,
                         cudaFuncAttributeMaxDynamicSharedMemorySize, GEMM_SMEM);

    convert_weights_kernel<<<3072, 256>>>(q_w, k_w, v_w, proj_w, fc1w, fc2w,
                                          wqkv, wp, wf1, wf2);
    concat3_kernel<<<6, 256>>>(q_b, k_b, v_b, qkvbias);

    ln1_gather_kernel<<<NTOK / 8, 256>>>(hid, ln1w, ln1b, xw);

    gemm_f16_kernel<<<dim3(QKVN / BN, NTOK / BM), 256, GEMM_SMEM>>>(
        xw, wqkv, qkvbias, qkvb, QKVN, CDIM, 0, nullptr);

    attn_kernel<<<dim3(1024, NHEADS), 64>>>(qkvb, relb, cx);

    gemm_f16_kernel<<<dim3(CDIM / BN, NTOK / BM), 256, GEMM_SMEM>>>(
        cx, wp, proj_b, hb, CDIM, CDIM, 4, hid);

    ln_plain_kernel<<<NTOK / 8, 256>>>(hb, ln2w, ln2b, yb);

    gemm_f16_kernel<<<dim3(MLPD / BN, NTOK / BM), 256, GEMM_SMEM>>>(
        yb, wf1, fc1b, mlp, MLPD, CDIM, 1, nullptr);

    gemm_f16_kernel<<<dim3(CDIM / BN, NTOK / BM), 256, GEMM_SMEM>>>(
        mlp, wf2, fc2b, out, CDIM, MLPD, 2, hb);
}